// round 1
// baseline (speedup 1.0000x reference)
#include <cuda_runtime.h>
#include <math.h>

#define BATCH 32
#define SEQ 4096
#define HIDDEN 2048
#define ROUTE_H 256
#define NUM_EXPERTS 64
#define TOP_K 8
#define LN_EPS 1e-5f

#define NSPLIT 16
#define SCHUNK (SEQ / NSPLIT)        // 256 rows per block
#define H4 (HIDDEN / 4)              // 512 float4 columns

// Scratch (no cudaMalloc allowed)
__device__ float g_partial[NSPLIT * BATCH * HIDDEN];   // [sp][b][h]  = 4 MB
__device__ float g_pooled[BATCH * HIDDEN];             // [b][h]

// ---------------------------------------------------------------------------
// Kernel 1: partial mean-pool. grid = BATCH*NSPLIT blocks, 512 threads.
// Each thread accumulates one float4 column over its 256-row seq slice.
// ---------------------------------------------------------------------------
__global__ void __launch_bounds__(512) pool_partial(const float* __restrict__ x) {
    int blk = blockIdx.x;
    int b   = blk / NSPLIT;
    int sp  = blk % NSPLIT;
    int c4  = threadIdx.x;  // 0..511

    const float4* base = (const float4*)(x) +
        ((size_t)b * SEQ + (size_t)sp * SCHUNK) * (size_t)H4 + c4;

    float4 acc = make_float4(0.f, 0.f, 0.f, 0.f);
#pragma unroll 8
    for (int s = 0; s < SCHUNK; s++) {
        float4 v = base[(size_t)s * H4];
        acc.x += v.x; acc.y += v.y; acc.z += v.z; acc.w += v.w;
    }

    float4* out = (float4*)(g_partial + ((size_t)sp * BATCH + b) * HIDDEN);
    out[c4] = acc;
}

// ---------------------------------------------------------------------------
// Kernel 2: fold the NSPLIT partials, scale by 1/SEQ.
// grid = BATCH*HIDDEN/256 blocks of 256 threads.
// ---------------------------------------------------------------------------
__global__ void __launch_bounds__(256) pool_reduce() {
    int idx = blockIdx.x * blockDim.x + threadIdx.x;  // 0 .. BATCH*HIDDEN-1
    float s = 0.f;
#pragma unroll
    for (int sp = 0; sp < NSPLIT; sp++)
        s += g_partial[(size_t)sp * BATCH * HIDDEN + idx];
    g_pooled[idx] = s * (1.0f / SEQ);
}

// ---------------------------------------------------------------------------
// Kernel 3: router MLP + LN + GELU + GEMV2 + top-8 softmax scatter.
// grid = BATCH blocks of ROUTE_H (256) threads. Block b handles batch row b.
// ---------------------------------------------------------------------------
__global__ void __launch_bounds__(ROUTE_H) router(
    const float* __restrict__ W1, const float* __restrict__ b1,
    const float* __restrict__ ln_g, const float* __restrict__ ln_b,
    const float* __restrict__ W2, const float* __restrict__ b2,
    float* __restrict__ out)
{
    __shared__ float sh_pooled[HIDDEN];
    __shared__ float sh_h[ROUTE_H];
    __shared__ float sh_red[ROUTE_H];
    __shared__ float sh_red2[ROUTE_H];
    __shared__ float sh_logits[NUM_EXPERTS];

    int b = blockIdx.x;
    int j = threadIdx.x;

    // Stage pooled row in shared (8 floats per thread)
#pragma unroll
    for (int k = 0; k < HIDDEN / ROUTE_H; k++)
        sh_pooled[k * ROUTE_H + j] = g_pooled[(size_t)b * HIDDEN + k * ROUTE_H + j];
    __syncthreads();

    // GEMV1: h[j] = pooled . W1[:, j] + b1[j]   (W1 row-major [HIDDEN, ROUTE_H])
    float acc0 = 0.f, acc1 = 0.f, acc2 = 0.f, acc3 = 0.f;
#pragma unroll 4
    for (int i = 0; i < HIDDEN; i += 4) {
        acc0 += sh_pooled[i + 0] * W1[(size_t)(i + 0) * ROUTE_H + j];
        acc1 += sh_pooled[i + 1] * W1[(size_t)(i + 1) * ROUTE_H + j];
        acc2 += sh_pooled[i + 2] * W1[(size_t)(i + 2) * ROUTE_H + j];
        acc3 += sh_pooled[i + 3] * W1[(size_t)(i + 3) * ROUTE_H + j];
    }
    float h = (acc0 + acc1) + (acc2 + acc3) + b1[j];

    // LayerNorm over ROUTE_H: block reduce sum and sumsq
    sh_red[j]  = h;
    sh_red2[j] = h * h;
    __syncthreads();
    for (int stride = ROUTE_H / 2; stride > 0; stride >>= 1) {
        if (j < stride) {
            sh_red[j]  += sh_red[j + stride];
            sh_red2[j] += sh_red2[j + stride];
        }
        __syncthreads();
    }
    float mu  = sh_red[0]  * (1.0f / ROUTE_H);
    float ms  = sh_red2[0] * (1.0f / ROUTE_H);
    float var = ms - mu * mu;
    float inv = rsqrtf(var + LN_EPS);

    h = (h - mu) * inv * ln_g[j] + ln_b[j];

    // exact GELU: 0.5*x*(1+erf(x/sqrt(2)))
    h = 0.5f * h * (1.0f + erff(h * 0.70710678118654752f));
    sh_h[j] = h;
    __syncthreads();

    // GEMV2: logits[j] = h . W2[:, j] + b2[j]   (W2 [ROUTE_H, NUM_EXPERTS])
    if (j < NUM_EXPERTS) {
        float a = b2[j];
#pragma unroll 8
        for (int i = 0; i < ROUTE_H; i++)
            a += sh_h[i] * W2[(size_t)i * NUM_EXPERTS + j];
        sh_logits[j] = a;
        out[(size_t)b * NUM_EXPERTS + j] = 0.0f;  // d_out is poisoned; zero first
    }
    __syncthreads();

    // top-8 + softmax + scatter (tiny; one thread). Strict '>' keeps first
    // index on ties, matching jax.lax.top_k ordering.
    if (j == 0) {
        int   idx[TOP_K];
        float val[TOP_K];
        bool  used[NUM_EXPERTS];
#pragma unroll
        for (int e = 0; e < NUM_EXPERTS; e++) used[e] = false;
        for (int t = 0; t < TOP_K; t++) {
            float best = -INFINITY;
            int bi = -1;
            for (int e = 0; e < NUM_EXPERTS; e++) {
                if (!used[e] && sh_logits[e] > best) { best = sh_logits[e]; bi = e; }
            }
            used[bi] = true;
            idx[t] = bi;
            val[t] = best;
        }
        float mx = val[0];
        float denom = 0.f;
        float ex[TOP_K];
        for (int t = 0; t < TOP_K; t++) { ex[t] = expf(val[t] - mx); denom += ex[t]; }
        float rden = 1.0f / denom;
        for (int t = 0; t < TOP_K; t++)
            out[(size_t)b * NUM_EXPERTS + idx[t]] = ex[t] * rden;
    }
}

// ---------------------------------------------------------------------------
extern "C" void kernel_launch(void* const* d_in, const int* in_sizes, int n_in,
                              void* d_out, int out_size) {
    const float* hs   = (const float*)d_in[0];
    const float* W1   = (const float*)d_in[1];
    const float* b1   = (const float*)d_in[2];
    const float* ln_g = (const float*)d_in[3];
    const float* ln_b = (const float*)d_in[4];
    const float* W2   = (const float*)d_in[5];
    const float* b2   = (const float*)d_in[6];
    // d_in[7] = top_k (hardcoded 8)

    float* out = (float*)d_out;

    pool_partial<<<BATCH * NSPLIT, 512>>>(hs);
    pool_reduce<<<(BATCH * HIDDEN) / 256, 256>>>();
    router<<<BATCH, ROUTE_H>>>(W1, b1, ln_g, ln_b, W2, b2, out);
}

// round 2
// speedup vs baseline: 1.2513x; 1.2513x over previous
#include <cuda_runtime.h>
#include <math.h>

#define BATCH 32
#define SEQ 4096
#define HIDDEN 2048
#define ROUTE_H 256
#define NUM_EXPERTS 64
#define TOP_K 8
#define LN_EPS 1e-5f

#define NSPLIT 32
#define SCHUNK (SEQ / NSPLIT)        // 128 rows per block
#define H4 (HIDDEN / 4)              // 512 float4 columns

#define RT_THREADS 1024
#define KSPLIT 4                     // K-split for GEMV1 (RT_THREADS / ROUTE_H)

// Scratch (no cudaMalloc allowed)
__device__ float g_partial[NSPLIT * BATCH * HIDDEN];   // [sp][b][h] = 8 MB

// ---------------------------------------------------------------------------
// Kernel 1: partial mean-pool. grid = BATCH*NSPLIT = 1024 blocks, 512 threads.
// Each thread accumulates one float4 column over its 128-row seq slice.
// ---------------------------------------------------------------------------
__global__ void __launch_bounds__(512) pool_partial(const float* __restrict__ x) {
    int blk = blockIdx.x;
    int b   = blk / NSPLIT;
    int sp  = blk % NSPLIT;
    int c4  = threadIdx.x;  // 0..511

    const float4* base = (const float4*)(x) +
        ((size_t)b * SEQ + (size_t)sp * SCHUNK) * (size_t)H4 + c4;

    float4 acc = make_float4(0.f, 0.f, 0.f, 0.f);
#pragma unroll 8
    for (int s = 0; s < SCHUNK; s++) {
        float4 v = base[(size_t)s * H4];
        acc.x += v.x; acc.y += v.y; acc.z += v.z; acc.w += v.w;
    }

    float4* out = (float4*)(g_partial + ((size_t)sp * BATCH + b) * HIDDEN);
    out[c4] = acc;
}

// ---------------------------------------------------------------------------
// Kernel 2 (fused): fold partials -> pooled, router MLP + LN + GELU + GEMV2 +
// top-8 softmax scatter. grid = BATCH blocks of 1024 threads.
// GEMV1 is K-split 4 ways: thread t handles output j = t&255, K-slice t>>8.
// ---------------------------------------------------------------------------
__global__ void __launch_bounds__(RT_THREADS) router_fused(
    const float* __restrict__ W1, const float* __restrict__ b1,
    const float* __restrict__ ln_g, const float* __restrict__ ln_b,
    const float* __restrict__ W2, const float* __restrict__ b2,
    float* __restrict__ out)
{
    __shared__ float sh_pooled[HIDDEN];        // 8 KB
    __shared__ float sh_part[RT_THREADS];      // 4 KB
    __shared__ float sh_h[ROUTE_H];
    __shared__ float sh_red[ROUTE_H];
    __shared__ float sh_red2[ROUTE_H];
    __shared__ float sh_logits[NUM_EXPERTS];

    int b = blockIdx.x;
    int t = threadIdx.x;

    // ---- fold NSPLIT partials into pooled row (in shared) ----
    // 1024 threads, 2048 columns -> 2 columns per thread.
#pragma unroll
    for (int k = 0; k < HIDDEN / RT_THREADS; k++) {
        int col = k * RT_THREADS + t;
        float s = 0.f;
#pragma unroll
        for (int sp = 0; sp < NSPLIT; sp++)
            s += g_partial[((size_t)sp * BATCH + b) * HIDDEN + col];
        sh_pooled[col] = s * (1.0f / SEQ);
    }
    __syncthreads();

    // ---- GEMV1, K-split 4: h[j] = pooled . W1[:, j] + b1[j] ----
    int j  = t & (ROUTE_H - 1);      // 0..255
    int ks = t >> 8;                 // 0..3
    int i0 = ks * (HIDDEN / KSPLIT); // 512-row K slice

    float a0 = 0.f, a1 = 0.f, a2 = 0.f, a3 = 0.f;
#pragma unroll 4
    for (int i = 0; i < HIDDEN / KSPLIT; i += 4) {
        int r = i0 + i;
        a0 += sh_pooled[r + 0] * W1[(size_t)(r + 0) * ROUTE_H + j];
        a1 += sh_pooled[r + 1] * W1[(size_t)(r + 1) * ROUTE_H + j];
        a2 += sh_pooled[r + 2] * W1[(size_t)(r + 2) * ROUTE_H + j];
        a3 += sh_pooled[r + 3] * W1[(size_t)(r + 3) * ROUTE_H + j];
    }
    sh_part[t] = (a0 + a1) + (a2 + a3);
    __syncthreads();

    float h = 0.f;
    if (t < ROUTE_H) {
        h = ((sh_part[j] + sh_part[j + 256]) +
             (sh_part[j + 512] + sh_part[j + 768])) + b1[j];

        // LayerNorm block reduce over 256 values
        sh_red[j]  = h;
        sh_red2[j] = h * h;
    }
    __syncthreads();
    for (int stride = ROUTE_H / 2; stride > 0; stride >>= 1) {
        if (t < stride) {
            sh_red[t]  += sh_red[t + stride];
            sh_red2[t] += sh_red2[t + stride];
        }
        __syncthreads();
    }

    if (t < ROUTE_H) {
        float mu  = sh_red[0]  * (1.0f / ROUTE_H);
        float ms  = sh_red2[0] * (1.0f / ROUTE_H);
        float inv = rsqrtf(ms - mu * mu + LN_EPS);
        h = (h - mu) * inv * ln_g[j] + ln_b[j];
        // exact GELU
        h = 0.5f * h * (1.0f + erff(h * 0.70710678118654752f));
        sh_h[j] = h;
    }
    __syncthreads();

    // ---- GEMV2, K-split 4: logits[e] = h . W2[:, e] + b2[e] ----
    if (t < NUM_EXPERTS * KSPLIT) {          // 256 threads
        int e   = t & (NUM_EXPERTS - 1);     // 0..63
        int ks2 = t >> 6;                    // 0..3
        int r0  = ks2 * (ROUTE_H / KSPLIT);  // 64-row slice
        float a = 0.f;
#pragma unroll 8
        for (int i = 0; i < ROUTE_H / KSPLIT; i++)
            a += sh_h[r0 + i] * W2[(size_t)(r0 + i) * NUM_EXPERTS + e];
        sh_part[t] = a;
    }
    __syncthreads();
    if (t < NUM_EXPERTS) {
        sh_logits[t] = ((sh_part[t] + sh_part[t + 64]) +
                        (sh_part[t + 128] + sh_part[t + 192])) + b2[t];
        out[(size_t)b * NUM_EXPERTS + t] = 0.0f;   // d_out poisoned; zero first
    }
    __syncthreads();

    // ---- top-8 + softmax + scatter (single thread; strict '>' matches
    // jax.lax.top_k first-index tie-break) ----
    if (t == 0) {
        int   idx[TOP_K];
        float val[TOP_K];
        unsigned long long used = 0ull;
        for (int k = 0; k < TOP_K; k++) {
            float best = -INFINITY;
            int bi = 0;
            for (int e = 0; e < NUM_EXPERTS; e++) {
                if (!((used >> e) & 1ull) && sh_logits[e] > best) {
                    best = sh_logits[e]; bi = e;
                }
            }
            used |= (1ull << bi);
            idx[k] = bi;
            val[k] = best;
        }
        float mx = val[0];
        float denom = 0.f;
        float ex[TOP_K];
        for (int k = 0; k < TOP_K; k++) { ex[k] = expf(val[k] - mx); denom += ex[k]; }
        float rden = 1.0f / denom;
        for (int k = 0; k < TOP_K; k++)
            out[(size_t)b * NUM_EXPERTS + idx[k]] = ex[k] * rden;
    }
}

// ---------------------------------------------------------------------------
extern "C" void kernel_launch(void* const* d_in, const int* in_sizes, int n_in,
                              void* d_out, int out_size) {
    const float* hs   = (const float*)d_in[0];
    const float* W1   = (const float*)d_in[1];
    const float* b1   = (const float*)d_in[2];
    const float* ln_g = (const float*)d_in[3];
    const float* ln_b = (const float*)d_in[4];
    const float* W2   = (const float*)d_in[5];
    const float* b2   = (const float*)d_in[6];
    // d_in[7] = top_k (hardcoded 8)

    float* out = (float*)d_out;

    pool_partial<<<BATCH * NSPLIT, 512>>>(hs);
    router_fused<<<BATCH, RT_THREADS>>>(W1, b1, ln_g, ln_b, W2, b2, out);
}

// round 3
// speedup vs baseline: 1.3763x; 1.0999x over previous
#include <cuda_runtime.h>
#include <math.h>

#define BATCH 32
#define SEQ 4096
#define HIDDEN 2048
#define ROUTE_H 256
#define NUM_EXPERTS 64
#define TOP_K 8
#define LN_EPS 1e-5f

#define NSPLIT 32
#define SCHUNK (SEQ / NSPLIT)        // 128 rows per block
#define H4 (HIDDEN / 4)              // 512 float4 columns

#define KB 8                         // K-split blocks for GEMV1
#define KCHUNK (HIDDEN / KB)         // 256 hidden cols per GEMV1 block

// Scratch (no cudaMalloc allowed)
__device__ float g_partial[NSPLIT * BATCH * HIDDEN];   // [sp][b][h] = 8 MB
__device__ float g_hpart[KB * BATCH * ROUTE_H];        // [ks][b][j] = 256 KB

// ---------------------------------------------------------------------------
// Kernel 1: partial mean-pool. grid = BATCH*NSPLIT = 1024 blocks, 512 threads.
// Each thread accumulates one float4 column over its 128-row seq slice.
// Streaming loads (__ldcs): the 1 GB input is touched once; keep it out of L2.
// ---------------------------------------------------------------------------
__global__ void __launch_bounds__(512) pool_partial(const float* __restrict__ x) {
    int blk = blockIdx.x;
    int b   = blk / NSPLIT;
    int sp  = blk % NSPLIT;
    int c4  = threadIdx.x;  // 0..511

    const float4* base = (const float4*)(x) +
        ((size_t)b * SEQ + (size_t)sp * SCHUNK) * (size_t)H4 + c4;

    float4 acc = make_float4(0.f, 0.f, 0.f, 0.f);
#pragma unroll 8
    for (int s = 0; s < SCHUNK; s++) {
        float4 v = __ldcs(&base[(size_t)s * H4]);
        acc.x += v.x; acc.y += v.y; acc.z += v.z; acc.w += v.w;
    }

    float4* out = (float4*)(g_partial + ((size_t)sp * BATCH + b) * HIDDEN);
    out[c4] = acc;
}

// ---------------------------------------------------------------------------
// Kernel 2: GEMV1 K-split across the grid. grid = BATCH*KB = 256 blocks,
// 256 threads. Block (b, ks): fold pooled cols [ks*256, ks*256+256), then
// partial h[j] = sum over those 256 rows of pooled[r] * W1[r][j].
// ---------------------------------------------------------------------------
__global__ void __launch_bounds__(ROUTE_H) gemv1_partial(
    const float* __restrict__ W1)
{
    __shared__ float sh_pool[KCHUNK];

    int blk = blockIdx.x;
    int b   = blk / KB;
    int ks  = blk % KB;
    int j   = threadIdx.x;           // 0..255
    int i0  = ks * KCHUNK;

    // Fold NSPLIT partials for this block's 256 pooled columns.
    // Thread j owns column i0+j: 32 loads, coalesced across threads.
    {
        float s = 0.f;
#pragma unroll
        for (int sp = 0; sp < NSPLIT; sp++)
            s += g_partial[((size_t)sp * BATCH + b) * HIDDEN + i0 + j];
        sh_pool[j] = s * (1.0f / SEQ);
    }
    __syncthreads();

    // Partial GEMV over 256 rows (coalesced W1 reads across j).
    float a0 = 0.f, a1 = 0.f, a2 = 0.f, a3 = 0.f;
    float a4 = 0.f, a5 = 0.f, a6 = 0.f, a7 = 0.f;
#pragma unroll 4
    for (int r = 0; r < KCHUNK; r += 8) {
        const float* w = W1 + (size_t)(i0 + r) * ROUTE_H + j;
        a0 += sh_pool[r + 0] * w[0 * ROUTE_H];
        a1 += sh_pool[r + 1] * w[1 * ROUTE_H];
        a2 += sh_pool[r + 2] * w[2 * ROUTE_H];
        a3 += sh_pool[r + 3] * w[3 * ROUTE_H];
        a4 += sh_pool[r + 4] * w[4 * ROUTE_H];
        a5 += sh_pool[r + 5] * w[5 * ROUTE_H];
        a6 += sh_pool[r + 6] * w[6 * ROUTE_H];
        a7 += sh_pool[r + 7] * w[7 * ROUTE_H];
    }
    float acc = ((a0 + a1) + (a2 + a3)) + ((a4 + a5) + (a6 + a7));

    g_hpart[((size_t)ks * BATCH + b) * ROUTE_H + j] = acc;
}

// ---------------------------------------------------------------------------
// Kernel 3: finale. grid = BATCH blocks, 256 threads.
// Fold KB h-partials + b1, LN, GELU, GEMV2, top-8 softmax scatter.
// ---------------------------------------------------------------------------
__global__ void __launch_bounds__(ROUTE_H) finale(
    const float* __restrict__ b1,
    const float* __restrict__ ln_g, const float* __restrict__ ln_b,
    const float* __restrict__ W2, const float* __restrict__ b2,
    float* __restrict__ out)
{
    __shared__ float sh_h[ROUTE_H];
    __shared__ float sh_w1[8], sh_w2[8];
    __shared__ float sh_part[ROUTE_H];
    __shared__ float sh_logits[NUM_EXPERTS];

    int b = blockIdx.x;
    int j = threadIdx.x;
    int lane = j & 31;
    int warp = j >> 5;

    // Fold KB partials
    float h = 0.f;
#pragma unroll
    for (int ks = 0; ks < KB; ks++)
        h += g_hpart[((size_t)ks * BATCH + b) * ROUTE_H + j];
    h += b1[j];

    // LN reduce via warp shuffles (8 warps)
    float s1 = h, s2 = h * h;
#pragma unroll
    for (int o = 16; o > 0; o >>= 1) {
        s1 += __shfl_xor_sync(0xffffffffu, s1, o);
        s2 += __shfl_xor_sync(0xffffffffu, s2, o);
    }
    if (lane == 0) { sh_w1[warp] = s1; sh_w2[warp] = s2; }
    __syncthreads();
    float t1 = sh_w1[lane & 7], t2 = sh_w2[lane & 7];
#pragma unroll
    for (int o = 4; o > 0; o >>= 1) {
        t1 += __shfl_xor_sync(0xffffffffu, t1, o);
        t2 += __shfl_xor_sync(0xffffffffu, t2, o);
    }
    t1 = __shfl_sync(0xffffffffu, t1, 0);
    t2 = __shfl_sync(0xffffffffu, t2, 0);

    float mu  = t1 * (1.0f / ROUTE_H);
    float ms  = t2 * (1.0f / ROUTE_H);
    float inv = rsqrtf(ms - mu * mu + LN_EPS);
    h = (h - mu) * inv * ln_g[j] + ln_b[j];
    // exact GELU
    h = 0.5f * h * (1.0f + erff(h * 0.70710678118654752f));
    sh_h[j] = h;
    __syncthreads();

    // GEMV2, K-split 4 within the block: 256 threads = 64 experts x 4 slices
    {
        int e   = j & (NUM_EXPERTS - 1);
        int ks2 = j >> 6;
        int r0  = ks2 * (ROUTE_H / 4);
        float a = 0.f;
#pragma unroll 8
        for (int i = 0; i < ROUTE_H / 4; i++)
            a += sh_h[r0 + i] * W2[(size_t)(r0 + i) * NUM_EXPERTS + e];
        sh_part[j] = a;
    }
    __syncthreads();
    if (j < NUM_EXPERTS) {
        sh_logits[j] = ((sh_part[j] + sh_part[j + 64]) +
                        (sh_part[j + 128] + sh_part[j + 192])) + b2[j];
        out[(size_t)b * NUM_EXPERTS + j] = 0.0f;   // d_out poisoned; zero first
    }
    __syncthreads();

    // top-8 + softmax + scatter (strict '>' = first-index tie-break, as
    // jax.lax.top_k)
    if (j == 0) {
        int   idx[TOP_K];
        float val[TOP_K];
        unsigned long long used = 0ull;
        for (int k = 0; k < TOP_K; k++) {
            float best = -INFINITY;
            int bi = 0;
            for (int e = 0; e < NUM_EXPERTS; e++) {
                if (!((used >> e) & 1ull) && sh_logits[e] > best) {
                    best = sh_logits[e]; bi = e;
                }
            }
            used |= (1ull << bi);
            idx[k] = bi;
            val[k] = best;
        }
        float mx = val[0];
        float denom = 0.f;
        float ex[TOP_K];
        for (int k = 0; k < TOP_K; k++) { ex[k] = expf(val[k] - mx); denom += ex[k]; }
        float rden = 1.0f / denom;
        for (int k = 0; k < TOP_K; k++)
            out[(size_t)b * NUM_EXPERTS + idx[k]] = ex[k] * rden;
    }
}

// ---------------------------------------------------------------------------
extern "C" void kernel_launch(void* const* d_in, const int* in_sizes, int n_in,
                              void* d_out, int out_size) {
    const float* hs   = (const float*)d_in[0];
    const float* W1   = (const float*)d_in[1];
    const float* b1   = (const float*)d_in[2];
    const float* ln_g = (const float*)d_in[3];
    const float* ln_b = (const float*)d_in[4];
    const float* W2   = (const float*)d_in[5];
    const float* b2   = (const float*)d_in[6];
    // d_in[7] = top_k (hardcoded 8)

    float* out = (float*)d_out;

    pool_partial<<<BATCH * NSPLIT, 512>>>(hs);
    gemv1_partial<<<BATCH * KB, ROUTE_H>>>(W1);
    finale<<<BATCH, ROUTE_H>>>(b1, ln_g, ln_b, W2, b2, out);
}